// round 1
// baseline (speedup 1.0000x reference)
#include <cuda_runtime.h>

// out[i] = cos(x[i,0] + w0), x: [N,2] float32 interleaved, N = 16777216.
// Memory-bound streaming kernel: read 128MB (x), write 64MB (out).
// Each thread processes 4 samples: 2x float4 loads, 1x float4 store.

__global__ void __launch_bounds__(256, 8)
hybrid_qnn_cos_kernel(const float4* __restrict__ x4,   // N/2 float4s (each = 2 samples)
                      const float* __restrict__ w,
                      float4* __restrict__ out4,       // N/4 float4s
                      int n_out4)                       // N/4
{
    const float w0 = __ldg(w);
    int idx = blockIdx.x * blockDim.x + threadIdx.x;
    int stride = gridDim.x * blockDim.x;

    for (int i = idx; i < n_out4; i += stride) {
        // samples 4i .. 4i+3  ->  x4[2i] = {x[4i,0],x[4i,1],x[4i+1,0],x[4i+1,1]}
        float4 a = __ldg(&x4[2 * i]);
        float4 b = __ldg(&x4[2 * i + 1]);
        float4 o;
        o.x = cosf(a.x + w0);
        o.y = cosf(a.z + w0);
        o.z = cosf(b.x + w0);
        o.w = cosf(b.z + w0);
        out4[i] = o;
    }
}

extern "C" void kernel_launch(void* const* d_in, const int* in_sizes, int n_in,
                              void* d_out, int out_size)
{
    const float4* x4 = (const float4*)d_in[0];   // x: [N,2] float32
    const float*  w  = (const float*)d_in[1];    // weights: [2] float32
    float4* out4 = (float4*)d_out;

    int n = in_sizes[0] / 2;        // number of samples N
    int n_out4 = n / 4;             // N divisible by 4 (N = 2^24)

    const int threads = 256;
    // Enough blocks for full occupancy with a short grid-stride loop.
    int blocks = (n_out4 + threads - 1) / threads;
    if (blocks > 16384) blocks = 16384;

    hybrid_qnn_cos_kernel<<<blocks, threads>>>(x4, w, out4, n_out4);
}